// round 15
// baseline (speedup 1.0000x reference)
#include <cuda_runtime.h>
#include <cuda_bf16.h>
#include <cstdint>

#define WARPS_PER_BLOCK 4
#define NTHR (32 * WARPS_PER_BLOCK)
#define CHUNK_BYTES 4096
#define CHUNK_F4 256               // float4 per 4 KB chunk
#define BQ_PER_WARP 2
#define NC_PER_BQ 8                // 4 head + 4 gaze

__device__ __forceinline__ float clip01(float v) { return fminf(fmaxf(v, 0.0f), 1.0f); }

__device__ __forceinline__ void mbar_init(unsigned int mbar, unsigned int count) {
    asm volatile("mbarrier.init.shared.b64 [%0], %1;" :: "r"(mbar), "r"(count) : "memory");
}
__device__ __forceinline__ void tma_issue(unsigned int dst, const void* src, unsigned int mbar) {
    asm volatile("mbarrier.arrive.expect_tx.shared.b64 _, [%0], %1;"
                 :: "r"(mbar), "r"((unsigned int)CHUNK_BYTES) : "memory");
    asm volatile("cp.async.bulk.shared::cluster.global.mbarrier::complete_tx::bytes "
                 "[%0], [%1], %2, [%3];"
                 :: "r"(dst), "l"(src), "r"((unsigned int)CHUNK_BYTES), "r"(mbar) : "memory");
}
__device__ __forceinline__ void mbar_wait(unsigned int mbar, unsigned int parity) {
    unsigned int done;
    asm volatile("{\n\t.reg .pred p;\n\t"
                 "mbarrier.try_wait.parity.acquire.cta.shared::cta.b64 p, [%1], %2;\n\t"
                 "selp.b32 %0, 1, 0, p;\n\t}"
                 : "=r"(done) : "r"(mbar), "r"(parity) : "memory");
    while (!done) {
        asm volatile("{\n\t.reg .pred p;\n\t"
                     "mbarrier.try_wait.parity.acquire.cta.shared::cta.b64 p, [%1], %2;\n\t"
                     "selp.b32 %0, 1, 0, p;\n\t}"
                     : "=r"(done) : "r"(mbar), "r"(parity) : "memory");
    }
}

// Finish one bq: mask combine, argmax reductions, bbox, epilogue, store.
// Warp-uniform; runs while the NEXT bq's TMA chunks are in flight.
__device__ __forceinline__ void finish_bq(
    int bq, int lane, float hmax, unsigned colnib, unsigned rml, unsigned rmh,
    float gmax, int gidx,
    const float* __restrict__ H, const float* __restrict__ C,
    const float* __restrict__ W, float* __restrict__ out)
{
    const size_t base = (size_t)bq * 4096;

    const unsigned c15 = lane & 15;
    unsigned mcl = (c15 < 8)  ? (colnib << (c15 * 4))       : 0u;
    unsigned mch = (c15 >= 8) ? (colnib << ((c15 - 8) * 4)) : 0u;
    const unsigned cl = __reduce_or_sync(0xffffffffu, mcl);
    const unsigned ch = __reduce_or_sync(0xffffffffu, mch);
    const unsigned rl = __reduce_or_sync(0xffffffffu, rml);
    const unsigned rh = __reduce_or_sync(0xffffffffu, rmh);

#pragma unroll
    for (int o = 16; o; o >>= 1) {
        hmax = fmaxf(hmax, __shfl_xor_sync(0xffffffffu, hmax, o));
        float gv2 = __shfl_xor_sync(0xffffffffu, gmax, o);
        int   gi2 = __shfl_xor_sync(0xffffffffu, gidx, o);
        if (gv2 > gmax || (gv2 == gmax && gi2 < gidx)) { gmax = gv2; gidx = gi2; }
    }

    int x1, x2, y1, y2;
    if ((cl | ch) != 0u) {
        unsigned long long cm = ((unsigned long long)ch << 32) | cl;
        unsigned long long rm = ((unsigned long long)rh << 32) | rl;
        x1 = __ffsll((long long)cm) - 1;
        x2 = 64 - __clzll((long long)cm);
        y1 = __ffsll((long long)rm) - 1;
        y2 = 64 - __clzll((long long)rm);
    } else {
        // Rare fallback: no head pixel >= 0.5 -> head argmax peak (L2-hot reload).
        const float4* h4 = reinterpret_cast<const float4*>(H + base);
        float pv = -1e30f; int pi = 0;
#pragma unroll 4
        for (int m = 0; m < 32; m++) {
            float4 v = h4[m * 32 + lane];
            float a[4] = {v.x, v.y, v.z, v.w};
#pragma unroll
            for (int k = 0; k < 4; k++) {
                float hv = clip01(a[k]);
                int idx = (m * 32 + lane) * 4 + k;
                if (hv > pv) { pv = hv; pi = idx; }
            }
        }
#pragma unroll
        for (int o = 16; o; o >>= 1) {
            float v2 = __shfl_xor_sync(0xffffffffu, pv, o);
            int   i2 = __shfl_xor_sync(0xffffffffu, pi, o);
            if (v2 > pv || (v2 == pv && i2 < pi)) { pv = v2; pi = i2; }
        }
        int px = pi & 63, py = pi >> 6;
        x1 = px; x2 = px + 1; y1 = py; y2 = py + 1;
    }

    const float conf_head = clip01(hmax);
    const float conf_gaze = clip01(gmax);
    const float gpx = fminf(fmaxf((float)(gidx & 63), 0.0f), 63.0f);
    const float gpy = fminf(fmaxf((float)(gidx >> 6), 0.0f), 63.0f);
    const float cx = (float)(x1 + x2) * 0.5f;
    const float cy = (float)(y1 + y2) * 0.5f;
    // jnp.round == round-half-to-even == rintf (cx/cy hit .5 exactly)
    const float hcx = fminf(fmaxf(rintf(cx), 0.0f), 63.0f);
    const float hcy = fminf(fmaxf(rintf(cy), 0.0f), 63.0f);
    const float dx = gpx - hcx, dy = gpy - hcy;
    const float stx = dx / 9.0f, sty = dy / 9.0f;   // linspace step, num=10

    float samp = 0.0f;
    if (lane < 10) {
        int xi = (int)rintf(hcx + (float)lane * stx);
        int yi = (int)rintf(hcy + (float)lane * sty);
        samp = clip01(__ldg(C + base + yi * 64 + xi));
    }
#pragma unroll
    for (int o = 16; o; o >>= 1) samp += __shfl_xor_sync(0xffffffffu, samp, o);

    if (lane == 0) {
        float norm = sqrtf(dx * dx + dy * dy);
        float dp = fminf(32.0f / norm - 1.0f, 0.0f);  // norm==0 -> +inf -> 0
        float score = samp / 10.0f + dp;
        float watch = W[bq];
        float r = (watch > 0.5f)
                ? (conf_head + (1.0f - conf_gaze) - score)
                : (conf_head + conf_gaze + score);
        out[bq] = r / 3.0f;
    }
}

__global__ __launch_bounds__(NTHR)
void gotd_eval_kernel(const float* __restrict__ G,   // gaze heatmaps   [n,64,64]
                      const float* __restrict__ H,   // head heatmaps   [n,64,64]
                      const float* __restrict__ C,   // connect heatmaps[n,64,64]
                      const float* __restrict__ W,   // watch_outside   [n]
                      float* __restrict__ out, int n)
{
    // [warp][buf][256 float4] = 4*2*4KB = 32 KB; + per-warp mbarrier pair.
    __shared__ float4 sbuf[WARPS_PER_BLOCK * 2 * CHUNK_F4];
    __shared__ unsigned long long smbar[WARPS_PER_BLOCK * 2];

    const int warp = threadIdx.x >> 5;
    const int lane = threadIdx.x & 31;
    const int bq0 = (blockIdx.x * WARPS_PER_BLOCK + warp) * BQ_PER_WARP;

    float4* wbuf = &sbuf[warp * 2 * CHUNK_F4];
    const unsigned int sbase = (unsigned int)__cvta_generic_to_shared(wbuf);
    const unsigned int mbase = (unsigned int)__cvta_generic_to_shared(&smbar[warp * 2]);

    if (lane == 0) {
        mbar_init(mbase, 1);
        mbar_init(mbase + 8, 1);
        asm volatile("fence.proxy.async.shared::cta;" ::: "memory");
    }
    __syncwarp();
    if (bq0 >= n) return;

    const int nbq = (bq0 + 1 < n) ? 2 : 1;
    const int NC = nbq * NC_PER_BQ;            // 8 or 16 chunks, continuous

    // Chunk c: bq = bq0 + c/8; cc = c%8; cc<4 -> head 4K-block cc, else gaze cc-4.
    auto chunk_src = [&](int c) -> const char* {
        const size_t b = (size_t)(bq0 + (c >> 3)) * 4096;
        const int cc = c & 7;
        const float* t = (cc < 4) ? H : G;
        return reinterpret_cast<const char*>(t + b) + (size_t)(cc & 3) * CHUNK_BYTES;
    };

    if (lane == 0) {
        tma_issue(sbase, chunk_src(0), mbase);
        if (NC > 1) tma_issue(sbase + CHUNK_BYTES, chunk_src(1), mbase + 8);
    }

    // Per-lane layout (as R3): slot s = m*32+lane; elem idx = s*4+k;
    // row = 2*m + (lane>>4); col = (lane&15)*4+k. Chunk cc holds m in [8cc',..).
    float hmax = -1e30f;
    unsigned colnib = 0, rml = 0, rmh = 0;
    float gmax = -1e30f; int gidx = 0;

#pragma unroll 1
    for (int c = 0; c < NC; c++) {
        const int b = c & 1;
        mbar_wait(mbase + b * 8, (c >> 1) & 1);
        const float4* buf = wbuf + b * CHUNK_F4;

        float4 v[8];
#pragma unroll
        for (int i = 0; i < 8; i++) v[i] = buf[i * 32 + lane];

        // Free the buffer immediately: keep the pipe full ACROSS the bq
        // boundary so bq0's epilogue below runs with bq1's chunks in flight.
        if (c + 2 < NC) {
            __syncwarp();
            if (lane == 0) {
                asm volatile("fence.proxy.async.shared::cta;" ::: "memory");
                tma_issue(sbase + b * CHUNK_BYTES, chunk_src(c + 2), mbase + b * 8);
            }
        }

        const int cc = c & 7;
        if (cc < 4) {
#pragma unroll
            for (int i = 0; i < 8; i++) {
                const int m = cc * 8 + i;
                float a[4] = {v[i].x, v[i].y, v[i].z, v[i].w};
                bool any5 = false;
#pragma unroll
                for (int k = 0; k < 4; k++) {
                    hmax = fmaxf(hmax, a[k]);
                    if (a[k] >= 0.5f) { colnib |= 1u << k; any5 = true; }
                }
                if (any5) {
                    int row = 2 * m + (lane >> 4);
                    if (row < 32) rml |= 1u << row; else rmh |= 1u << (row - 32);
                }
            }
        } else {
#pragma unroll
            for (int i = 0; i < 8; i++) {
                const int m = (cc - 4) * 8 + i;
                float a[4] = {v[i].x, v[i].y, v[i].z, v[i].w};
#pragma unroll
                for (int k = 0; k < 4; k++) {
                    // raw-value argmax; clip01 on scalar max in finish_bq
                    // (inputs in [0,1): elementwise clip is identity; strict >
                    // keeps first-index semantics).
                    int idx = (m * 32 + lane) * 4 + k;
                    if (a[k] > gmax) { gmax = a[k]; gidx = idx; }
                }
            }
        }

        if (cc == 7) {   // bq (bq0 + c/8) complete: finish while pipe keeps running
            finish_bq(bq0 + (c >> 3), lane, hmax, colnib, rml, rmh, gmax, gidx,
                      H, C, W, out);
            hmax = -1e30f; colnib = 0; rml = 0; rmh = 0;
            gmax = -1e30f; gidx = 0;
        }
    }
}

extern "C" void kernel_launch(void* const* d_in, const int* in_sizes, int n_in,
                              void* d_out, int out_size) {
    const float* G = (const float*)d_in[0];  // pred_gaze_heatmap
    const float* H = (const float*)d_in[1];  // pred_head_heatmap
    const float* C = (const float*)d_in[2];  // pred_connect_heatmap
    const float* W = (const float*)d_in[3];  // pred_gaze_watch_outside
    float* out = (float*)d_out;
    int n = in_sizes[3];                     // B*Q = 8192
    int warps = (n + BQ_PER_WARP - 1) / BQ_PER_WARP;          // 4096
    int grid = (warps + WARPS_PER_BLOCK - 1) / WARPS_PER_BLOCK; // 1024
    gotd_eval_kernel<<<grid, NTHR>>>(G, H, C, W, out, n);
}

// round 16
// speedup vs baseline: 1.1413x; 1.1413x over previous
#include <cuda_runtime.h>
#include <cuda_bf16.h>
#include <cstdint>

#define NTHR 128
#define GROUPS_PER_BLOCK 2         // 64-thread groups; 1 bq per group
#define GSIZE 64
#define CHUNK_BYTES 4096
#define CHUNK_F4 256               // float4 per 4 KB chunk
#define NCHUNK 8                   // 4 head + 4 gaze per bq

__device__ __forceinline__ float clip01(float v) { return fminf(fmaxf(v, 0.0f), 1.0f); }

__device__ __forceinline__ void mbar_init(unsigned int mbar, unsigned int count) {
    asm volatile("mbarrier.init.shared.b64 [%0], %1;" :: "r"(mbar), "r"(count) : "memory");
}
__device__ __forceinline__ void tma_issue(unsigned int dst, const void* src, unsigned int mbar) {
    asm volatile("mbarrier.arrive.expect_tx.shared.b64 _, [%0], %1;"
                 :: "r"(mbar), "r"((unsigned int)CHUNK_BYTES) : "memory");
    asm volatile("cp.async.bulk.shared::cluster.global.mbarrier::complete_tx::bytes "
                 "[%0], [%1], %2, [%3];"
                 :: "r"(dst), "l"(src), "r"((unsigned int)CHUNK_BYTES), "r"(mbar) : "memory");
}
__device__ __forceinline__ void mbar_wait(unsigned int mbar, unsigned int parity) {
    unsigned int done;
    asm volatile("{\n\t.reg .pred p;\n\t"
                 "mbarrier.try_wait.parity.acquire.cta.shared::cta.b64 p, [%1], %2;\n\t"
                 "selp.b32 %0, 1, 0, p;\n\t}"
                 : "=r"(done) : "r"(mbar), "r"(parity) : "memory");
    while (!done) {
        asm volatile("{\n\t.reg .pred p;\n\t"
                     "mbarrier.try_wait.parity.acquire.cta.shared::cta.b64 p, [%1], %2;\n\t"
                     "selp.b32 %0, 1, 0, p;\n\t}"
                     : "=r"(done) : "r"(mbar), "r"(parity) : "memory");
    }
}
__device__ __forceinline__ void gbar(int id) {      // 64-thread named barrier
    asm volatile("bar.sync %0, %1;" :: "r"(id), "r"(GSIZE) : "memory");
}

__global__ __launch_bounds__(NTHR)
void gotd_eval_kernel(const float* __restrict__ G,   // gaze heatmaps   [n,64,64]
                      const float* __restrict__ H,   // head heatmaps   [n,64,64]
                      const float* __restrict__ C,   // connect heatmaps[n,64,64]
                      const float* __restrict__ W,   // watch_outside   [n]
                      float* __restrict__ out, int n)
{
    // [group][buf][256 float4] = 2*2*4KB = 16 KB  -> ~13 CTAs/SM.
    __shared__ float4 sbuf[GROUPS_PER_BLOCK * 2 * CHUNK_F4];
    __shared__ unsigned long long smbar[GROUPS_PER_BLOCK * 2];
    __shared__ unsigned smask[GROUPS_PER_BLOCK][4];   // cl, ch, rl, rh
    __shared__ float shm[GROUPS_PER_BLOCK][2];        // per-warp hmax
    __shared__ float sgm[GROUPS_PER_BLOCK][2];        // per-warp gmax
    __shared__ int   sgi[GROUPS_PER_BLOCK][2];        // per-warp gidx

    const int tid  = threadIdx.x;
    const int g    = tid >> 6;       // group in CTA
    const int gt   = tid & 63;       // thread in group
    const int wing = gt >> 5;        // warp in group (0/1)
    const int lane = tid & 31;
    const int bq   = blockIdx.x * GROUPS_PER_BLOCK + g;
    const int barid = 1 + g;         // named barrier id (0 reserved)

    float4* gb = &sbuf[g * 2 * CHUNK_F4];
    const unsigned int sbase = (unsigned int)__cvta_generic_to_shared(gb);
    const unsigned int mbase = (unsigned int)__cvta_generic_to_shared(&smbar[g * 2]);

    if (gt == 0) {
        mbar_init(mbase, 1);
        mbar_init(mbase + 8, 1);
        smask[g][0] = smask[g][1] = smask[g][2] = smask[g][3] = 0u;
        asm volatile("fence.proxy.async.shared::cta;" ::: "memory");
    }
    gbar(barid);                     // whole group past init (group-scoped)
    if (bq >= n) return;             // group exits together

    const size_t base = (size_t)bq * 4096;
    const char* hsrc = reinterpret_cast<const char*>(H + base);
    const char* gsrc = reinterpret_cast<const char*>(G + base);
    auto chunk_src = [&](int c) -> const char* {
        return (c < 4) ? hsrc + c * CHUNK_BYTES : gsrc + (c - 4) * CHUNK_BYTES;
    };

    if (gt == 0) {
        tma_issue(sbase, chunk_src(0), mbase);
        tma_issue(sbase + CHUNK_BYTES, chunk_src(1), mbase + 8);
    }

    // Layout: tile = 1024 float4, linear index f; row=f>>4, col=(f&15)*4+k,
    // elem idx=f*4+k. Chunk c covers f in [256c', 256c'+256); thread gt owns
    // f = 256c' + i*64 + gt (i=0..3). Note (f&15) == (gt&15): col fixed/thread.
    float hmax = -1e30f;
    unsigned colnib = 0, rml = 0, rmh = 0;
    float gmax = -1e30f; int gidx = 0;

#pragma unroll
    for (int c = 0; c < NCHUNK; c++) {
        const int b = c & 1;
        mbar_wait(mbase + b * 8, (c >> 1) & 1);
        const float4* buf = gb + b * CHUNK_F4;

        float4 v[4];
#pragma unroll
        for (int i = 0; i < 4; i++) v[i] = buf[i * 64 + gt];

        gbar(barid);                 // both warps done reading buffer b
        if (gt == 0 && c + 2 < NCHUNK) {
            asm volatile("fence.proxy.async.shared::cta;" ::: "memory");
            tma_issue(sbase + b * CHUNK_BYTES, chunk_src(c + 2), mbase + b * 8);
        }

        if (c < 4) {
#pragma unroll
            for (int i = 0; i < 4; i++) {
                const int f = c * 256 + i * 64 + gt;
                float a[4] = {v[i].x, v[i].y, v[i].z, v[i].w};
                bool any5 = false;
#pragma unroll
                for (int k = 0; k < 4; k++) {
                    hmax = fmaxf(hmax, a[k]);
                    if (a[k] >= 0.5f) { colnib |= 1u << k; any5 = true; }
                }
                if (any5) {
                    int row = f >> 4;
                    if (row < 32) rml |= 1u << row; else rmh |= 1u << (row - 32);
                }
            }
        } else {
#pragma unroll
            for (int i = 0; i < 4; i++) {
                const int f = (c - 4) * 256 + i * 64 + gt;
                float a[4] = {v[i].x, v[i].y, v[i].z, v[i].w};
#pragma unroll
                for (int k = 0; k < 4; k++) {
                    // raw-value argmax; clip01 on scalar max below (inputs in
                    // [0,1): elementwise clip is identity; strict > keeps
                    // first-index semantics; min-idx tie-break in reductions).
                    int idx = f * 4 + k;
                    if (a[k] > gmax) { gmax = a[k]; gidx = idx; }
                }
            }
        }
    }

    // ---- per-warp reductions ----
    const unsigned c15 = gt & 15;
    unsigned mcl = (c15 < 8)  ? (colnib << (c15 * 4))       : 0u;
    unsigned mch = (c15 >= 8) ? (colnib << ((c15 - 8) * 4)) : 0u;
    unsigned cl = __reduce_or_sync(0xffffffffu, mcl);
    unsigned ch = __reduce_or_sync(0xffffffffu, mch);
    unsigned rl = __reduce_or_sync(0xffffffffu, rml);
    unsigned rh = __reduce_or_sync(0xffffffffu, rmh);
#pragma unroll
    for (int o = 16; o; o >>= 1) {
        hmax = fmaxf(hmax, __shfl_xor_sync(0xffffffffu, hmax, o));
        float gv2 = __shfl_xor_sync(0xffffffffu, gmax, o);
        int   gi2 = __shfl_xor_sync(0xffffffffu, gidx, o);
        if (gv2 > gmax || (gv2 == gmax && gi2 < gidx)) { gmax = gv2; gidx = gi2; }
    }
    if (lane == 0) {
        atomicOr(&smask[g][0], cl); atomicOr(&smask[g][1], ch);
        atomicOr(&smask[g][2], rl); atomicOr(&smask[g][3], rh);
        shm[g][wing] = hmax; sgm[g][wing] = gmax; sgi[g][wing] = gidx;
    }
    gbar(barid);

    // ---- warp 0 of the group finishes the bq ----
    if (wing == 0) {
        float hm = fmaxf(shm[g][0], shm[g][1]);
        float gm = sgm[g][0]; int gi = sgi[g][0];
        if (sgm[g][1] > gm || (sgm[g][1] == gm && sgi[g][1] < gi)) { gm = sgm[g][1]; gi = sgi[g][1]; }
        unsigned CL = smask[g][0], CH = smask[g][1], RL = smask[g][2], RH = smask[g][3];

        int x1, x2, y1, y2;
        if ((CL | CH) != 0u) {
            unsigned long long cm = ((unsigned long long)CH << 32) | CL;
            unsigned long long rm = ((unsigned long long)RH << 32) | RL;
            x1 = __ffsll((long long)cm) - 1;
            x2 = 64 - __clzll((long long)cm);
            y1 = __ffsll((long long)rm) - 1;
            y2 = 64 - __clzll((long long)rm);
        } else {
            // Rare fallback: head argmax peak (L2-hot reload; warp0 only).
            const float4* h4 = reinterpret_cast<const float4*>(H + base);
            float pv = -1e30f; int pi = 0;
#pragma unroll 4
            for (int m = 0; m < 32; m++) {
                float4 v = h4[m * 32 + lane];
                float a[4] = {v.x, v.y, v.z, v.w};
#pragma unroll
                for (int k = 0; k < 4; k++) {
                    float hv = clip01(a[k]);
                    int idx = (m * 32 + lane) * 4 + k;
                    if (hv > pv) { pv = hv; pi = idx; }
                }
            }
#pragma unroll
            for (int o = 16; o; o >>= 1) {
                float v2 = __shfl_xor_sync(0xffffffffu, pv, o);
                int   i2 = __shfl_xor_sync(0xffffffffu, pi, o);
                if (v2 > pv || (v2 == pv && i2 < pi)) { pv = v2; pi = i2; }
            }
            int px = pi & 63, py = pi >> 6;
            x1 = px; x2 = px + 1; y1 = py; y2 = py + 1;
        }

        const float conf_head = clip01(hm);
        const float conf_gaze = clip01(gm);
        const float gpx = fminf(fmaxf((float)(gi & 63), 0.0f), 63.0f);
        const float gpy = fminf(fmaxf((float)(gi >> 6), 0.0f), 63.0f);
        const float cx = (float)(x1 + x2) * 0.5f;
        const float cy = (float)(y1 + y2) * 0.5f;
        // jnp.round == round-half-to-even == rintf (cx/cy hit .5 exactly)
        const float hcx = fminf(fmaxf(rintf(cx), 0.0f), 63.0f);
        const float hcy = fminf(fmaxf(rintf(cy), 0.0f), 63.0f);
        const float dx = gpx - hcx, dy = gpy - hcy;
        const float stx = dx / 9.0f, sty = dy / 9.0f;   // linspace step, num=10

        float samp = 0.0f;
        if (lane < 10) {
            int xi = (int)rintf(hcx + (float)lane * stx);
            int yi = (int)rintf(hcy + (float)lane * sty);
            samp = clip01(__ldg(C + base + yi * 64 + xi));
        }
#pragma unroll
        for (int o = 16; o; o >>= 1) samp += __shfl_xor_sync(0xffffffffu, samp, o);

        if (lane == 0) {
            float norm = sqrtf(dx * dx + dy * dy);
            float dp = fminf(32.0f / norm - 1.0f, 0.0f);  // norm==0 -> +inf -> 0
            float score = samp / 10.0f + dp;
            float watch = W[bq];
            float r = (watch > 0.5f)
                    ? (conf_head + (1.0f - conf_gaze) - score)
                    : (conf_head + conf_gaze + score);
            out[bq] = r / 3.0f;
        }
    }
}

extern "C" void kernel_launch(void* const* d_in, const int* in_sizes, int n_in,
                              void* d_out, int out_size) {
    const float* G = (const float*)d_in[0];  // pred_gaze_heatmap
    const float* H = (const float*)d_in[1];  // pred_head_heatmap
    const float* C = (const float*)d_in[2];  // pred_connect_heatmap
    const float* W = (const float*)d_in[3];  // pred_gaze_watch_outside
    float* out = (float*)d_out;
    int n = in_sizes[3];                     // B*Q = 8192
    int grid = (n + GROUPS_PER_BLOCK - 1) / GROUPS_PER_BLOCK;   // 4096
    gotd_eval_kernel<<<grid, NTHR>>>(G, H, C, W, out, n);
}

// round 17
// speedup vs baseline: 1.2463x; 1.0920x over previous
#include <cuda_runtime.h>
#include <cuda_bf16.h>
#include <cstdint>

#define WARPS_PER_BLOCK 4
#define NTHR (32 * WARPS_PER_BLOCK)
#define CHUNK_BYTES 8192
#define CHUNK_F4 512               // float4 per 8 KB chunk
#define NCHUNK 4                   // 2 head + 2 gaze per bq

__device__ __forceinline__ float clip01(float v) { return fminf(fmaxf(v, 0.0f), 1.0f); }

__device__ __forceinline__ void mbar_init(unsigned int mbar, unsigned int count) {
    asm volatile("mbarrier.init.shared.b64 [%0], %1;" :: "r"(mbar), "r"(count) : "memory");
}
__device__ __forceinline__ void tma_issue(unsigned int dst, const void* src, unsigned int mbar) {
    asm volatile("mbarrier.arrive.expect_tx.shared.b64 _, [%0], %1;"
                 :: "r"(mbar), "r"((unsigned int)CHUNK_BYTES) : "memory");
    asm volatile("cp.async.bulk.shared::cluster.global.mbarrier::complete_tx::bytes "
                 "[%0], [%1], %2, [%3];"
                 :: "r"(dst), "l"(src), "r"((unsigned int)CHUNK_BYTES), "r"(mbar) : "memory");
}
__device__ __forceinline__ void mbar_wait(unsigned int mbar, unsigned int parity) {
    unsigned int done;
    asm volatile("{\n\t.reg .pred p;\n\t"
                 "mbarrier.try_wait.parity.acquire.cta.shared::cta.b64 p, [%1], %2;\n\t"
                 "selp.b32 %0, 1, 0, p;\n\t}"
                 : "=r"(done) : "r"(mbar), "r"(parity) : "memory");
    while (!done) {
        asm volatile("{\n\t.reg .pred p;\n\t"
                     "mbarrier.try_wait.parity.acquire.cta.shared::cta.b64 p, [%1], %2;\n\t"
                     "selp.b32 %0, 1, 0, p;\n\t}"
                     : "=r"(done) : "r"(mbar), "r"(parity) : "memory");
    }
}

__global__ __launch_bounds__(NTHR)
void gotd_eval_kernel(const float* __restrict__ G,   // gaze heatmaps   [n,64,64]
                      const float* __restrict__ H,   // head heatmaps   [n,64,64]
                      const float* __restrict__ C,   // connect heatmaps[n,64,64]
                      const float* __restrict__ W,   // watch_outside   [n]
                      float* __restrict__ out, int n)
{
    // [warp][buf][512 float4] = 4*2*8KB = 64 KB; + per-warp mbarrier pair.
    __shared__ float4 sbuf[WARPS_PER_BLOCK * 2 * CHUNK_F4];
    __shared__ unsigned long long smbar[WARPS_PER_BLOCK * 2];

    const int warp = threadIdx.x >> 5;
    const int lane = threadIdx.x & 31;
    const int bq = blockIdx.x * WARPS_PER_BLOCK + warp;

    float4* wbuf = &sbuf[warp * 2 * CHUNK_F4];
    const unsigned int sb0 = (unsigned int)__cvta_generic_to_shared(wbuf);
    const unsigned int sb1 = sb0 + CHUNK_BYTES;
    const unsigned int mb0 = (unsigned int)__cvta_generic_to_shared(&smbar[warp * 2]);
    const unsigned int mb1 = mb0 + 8;

    // Per-warp init; no cross-warp coupling, no __syncthreads.
    if (lane == 0) {
        mbar_init(mb0, 1);
        mbar_init(mb1, 1);
        asm volatile("fence.proxy.async.shared::cta;" ::: "memory");
    }
    __syncwarp();
    if (bq >= n) return;

    const size_t base = (size_t)bq * 4096;
    const char* hsrc = reinterpret_cast<const char*>(H + base);
    const char* gsrc = reinterpret_cast<const char*>(G + base);

    // Chunk c: c<2 -> head bytes [c*8K,(c+1)*8K), else gaze [(c-2)*8K,...).
    auto chunk_src = [&](int c) -> const char* {
        return (c < 2) ? hsrc + c * CHUNK_BYTES : gsrc + (c - 2) * CHUNK_BYTES;
    };

    if (lane == 0) {
        tma_issue(sb0, chunk_src(0), mb0);
        tma_issue(sb1, chunk_src(1), mb1);
    }

    // Per-lane layout (as R3): global slot s = m*32+lane (m=0..31);
    // elem idx = s*4+k; row = 2*m + (lane>>4); col = (lane&15)*4+k.
    // Chunk c covers m in [16c', 16c'+16).
    float hmax = -1e30f;
    unsigned colnib = 0, rml = 0, rmh = 0;
    float gmax = -1e30f; int gidx = 0;

#pragma unroll
    for (int c = 0; c < NCHUNK; c++) {
        const unsigned int mb = (c & 1) ? mb1 : mb0;
        const float4* buf = wbuf + (c & 1) * CHUNK_F4;
        mbar_wait(mb, (c >> 1) & 1);

        // Two sub-batches of 8 float4 (register pressure as R11).
#pragma unroll
        for (int hblk = 0; hblk < 2; hblk++) {
            float4 v[8];
#pragma unroll
            for (int i = 0; i < 8; i++) v[i] = buf[(hblk * 8 + i) * 32 + lane];

            if (c < 2) {
#pragma unroll
                for (int i = 0; i < 8; i++) {
                    const int m = c * 16 + hblk * 8 + i;
                    float a[4] = {v[i].x, v[i].y, v[i].z, v[i].w};
                    bool any5 = false;
#pragma unroll
                    for (int k = 0; k < 4; k++) {
                        hmax = fmaxf(hmax, a[k]);
                        if (a[k] >= 0.5f) { colnib |= 1u << k; any5 = true; }
                    }
                    if (any5) {
                        int row = 2 * m + (lane >> 4);
                        if (row < 32) rml |= 1u << row; else rmh |= 1u << (row - 32);
                    }
                }
            } else {
#pragma unroll
                for (int i = 0; i < 8; i++) {
                    const int m = (c - 2) * 16 + hblk * 8 + i;
                    float a[4] = {v[i].x, v[i].y, v[i].z, v[i].w};
#pragma unroll
                    for (int k = 0; k < 4; k++) {
                        // raw-value argmax; clip01 on scalar max below (inputs
                        // in [0,1): elementwise clip is identity; strict >
                        // keeps first-index semantics).
                        int idx = (m * 32 + lane) * 4 + k;
                        if (a[k] > gmax) { gmax = a[k]; gidx = idx; }
                    }
                }
            }
        }

        if (c + 2 < NCHUNK) {
            __syncwarp();
            if (lane == 0) {
                asm volatile("fence.proxy.async.shared::cta;" ::: "memory");
                tma_issue((c & 1) ? sb1 : sb0, chunk_src(c + 2), mb);
            }
        }
    }

    // ---- warp-wide masks via REDUX (uniform result in all lanes) ----
    const unsigned c15 = lane & 15;
    unsigned mcl = (c15 < 8)  ? (colnib << (c15 * 4))       : 0u;
    unsigned mch = (c15 >= 8) ? (colnib << ((c15 - 8) * 4)) : 0u;
    const unsigned cl = __reduce_or_sync(0xffffffffu, mcl);
    const unsigned ch = __reduce_or_sync(0xffffffffu, mch);
    const unsigned rl = __reduce_or_sync(0xffffffffu, rml);
    const unsigned rh = __reduce_or_sync(0xffffffffu, rmh);

    // ---- butterfly reductions: every lane ends with the warp result ----
#pragma unroll
    for (int o = 16; o; o >>= 1) {
        hmax = fmaxf(hmax, __shfl_xor_sync(0xffffffffu, hmax, o));
        float gv2 = __shfl_xor_sync(0xffffffffu, gmax, o);
        int   gi2 = __shfl_xor_sync(0xffffffffu, gidx, o);
        if (gv2 > gmax || (gv2 == gmax && gi2 < gidx)) { gmax = gv2; gidx = gi2; }
    }

    // ---- bbox (rare fallback: no pixel >= 0.5 -> head peak, warp-uniform) ----
    int x1, x2, y1, y2;
    if ((cl | ch) != 0u) {
        unsigned long long cm = ((unsigned long long)ch << 32) | cl;
        unsigned long long rm = ((unsigned long long)rh << 32) | rl;
        x1 = __ffsll((long long)cm) - 1;
        x2 = 64 - __clzll((long long)cm);
        y1 = __ffsll((long long)rm) - 1;
        y2 = 64 - __clzll((long long)rm);
    } else {
        const float4* h4 = reinterpret_cast<const float4*>(H + base);
        float pv = -1e30f; int pi = 0;
#pragma unroll 4
        for (int m = 0; m < 32; m++) {
            float4 v = h4[m * 32 + lane];          // rare reload (L2-hot)
            float a[4] = {v.x, v.y, v.z, v.w};
#pragma unroll
            for (int k = 0; k < 4; k++) {
                float hv = clip01(a[k]);
                int idx = (m * 32 + lane) * 4 + k;
                if (hv > pv) { pv = hv; pi = idx; }
            }
        }
#pragma unroll
        for (int o = 16; o; o >>= 1) {
            float v2 = __shfl_xor_sync(0xffffffffu, pv, o);
            int   i2 = __shfl_xor_sync(0xffffffffu, pi, o);
            if (v2 > pv || (v2 == pv && i2 < pi)) { pv = v2; pi = i2; }
        }
        int px = pi & 63, py = pi >> 6;
        x1 = px; x2 = px + 1; y1 = py; y2 = py + 1;
    }

    // ---- epilogue (warp-uniform; 10 connect samples on lanes 0-9) ----
    const float conf_head = clip01(hmax);
    const float conf_gaze = clip01(gmax);
    const float gpx = fminf(fmaxf((float)(gidx & 63), 0.0f), 63.0f);
    const float gpy = fminf(fmaxf((float)(gidx >> 6), 0.0f), 63.0f);
    const float cx = (float)(x1 + x2) * 0.5f;
    const float cy = (float)(y1 + y2) * 0.5f;
    // jnp.round == round-half-to-even == rintf (cx/cy hit .5 exactly)
    const float hcx = fminf(fmaxf(rintf(cx), 0.0f), 63.0f);
    const float hcy = fminf(fmaxf(rintf(cy), 0.0f), 63.0f);
    const float dx = gpx - hcx, dy = gpy - hcy;
    const float stx = dx / 9.0f, sty = dy / 9.0f;   // linspace step, num=10

    float samp = 0.0f;
    if (lane < 10) {
        int xi = (int)rintf(hcx + (float)lane * stx);
        int yi = (int)rintf(hcy + (float)lane * sty);
        samp = clip01(__ldg(C + base + yi * 64 + xi));
    }
#pragma unroll
    for (int o = 16; o; o >>= 1) samp += __shfl_xor_sync(0xffffffffu, samp, o);

    if (lane == 0) {
        float norm = sqrtf(dx * dx + dy * dy);
        float dp = fminf(32.0f / norm - 1.0f, 0.0f);  // norm==0 -> +inf -> 0
        float score = samp / 10.0f + dp;
        float watch = W[bq];
        float r = (watch > 0.5f)
                ? (conf_head + (1.0f - conf_gaze) - score)
                : (conf_head + conf_gaze + score);
        out[bq] = r / 3.0f;
    }
}

extern "C" void kernel_launch(void* const* d_in, const int* in_sizes, int n_in,
                              void* d_out, int out_size) {
    const float* G = (const float*)d_in[0];  // pred_gaze_heatmap
    const float* H = (const float*)d_in[1];  // pred_head_heatmap
    const float* C = (const float*)d_in[2];  // pred_connect_heatmap
    const float* W = (const float*)d_in[3];  // pred_gaze_watch_outside
    float* out = (float*)d_out;
    int n = in_sizes[3];                     // B*Q = 8192
    int grid = (n + WARPS_PER_BLOCK - 1) / WARPS_PER_BLOCK;   // 2048
    gotd_eval_kernel<<<grid, NTHR>>>(G, H, C, W, out, n);
}